// round 1
// baseline (speedup 1.0000x reference)
#include <cuda_runtime.h>

#define DIM 2048
#define SEQ 8192
#define NH 16
#define HD 128
#define PD 512
#define LNEPS 1e-5f
#define RSQRT_D 0.08838834764831845f  /* 1/sqrt(128) */

#define N_SCHUNK 64   /* ctx split-K chunks (128 rows each) */

// ---------------- static scratch (no allocations allowed) ----------------
__device__ __align__(16) float g_qW[NH * DIM];     // qW[h][j]
__device__ float g_qb[NH];                          // q_h . b_k_h
__device__ __align__(16) float g_attn[NH * SEQ];    // logits, then softmax in place
__device__ __align__(16) float g_partial[N_SCHUNK * NH * DIM];
__device__ __align__(16) float g_ctx[NH * DIM];
__device__ __align__(16) float g_x1[DIM];
__device__ __align__(16) float g_h1[PD];
__device__ __align__(16) float g_h1n[PD];
__device__ __align__(16) float g_y[DIM];

// ---------------- K0: qW[h][j] = sum_d q[h*128+d] * W_kv[h*128+d][j] ------
__global__ void k_qw(const float* __restrict__ q, const float* __restrict__ Wkv) {
    int tid = blockIdx.x * 256 + threadIdx.x;   // 0..32767
    int h = tid >> 11;
    int j = tid & (DIM - 1);
    const float* qh = q + h * HD;
    const float* wcol = Wkv + (size_t)(h * HD) * DIM + j;
    float acc = 0.f;
#pragma unroll 8
    for (int d = 0; d < HD; d++)
        acc += qh[d] * wcol[(size_t)d * DIM];
    g_qW[tid] = acc;
}

// qb[h] = q_h . b_k_h   (one CTA, warp per head)
__global__ void k_qb(const float* __restrict__ q, const float* __restrict__ bkv) {
    int t = threadIdx.x;
    int h = t >> 5, l = t & 31;
    float a = 0.f;
#pragma unroll
    for (int d = l; d < HD; d += 32) a += q[h * HD + d] * bkv[h * HD + d];
#pragma unroll
    for (int o = 16; o; o >>= 1) a += __shfl_xor_sync(0xffffffffu, a, o);
    if (l == 0) g_qb[h] = a;
}

// ---------------- K1: logits = x @ qW^T, scaled ----------------
// grid 128, 64 threads. Tile: 64 rows x 16 heads, 4x4 per thread, KT=64.
__global__ void __launch_bounds__(64) k_logits(const float* __restrict__ x) {
    __shared__ float xs[64][68];  // [k][r], 16B-aligned rows
    __shared__ float qs[64][20];  // [k][h]
    int t = threadIdx.x;
    int s0 = blockIdx.x * 64;
    int rg = t >> 2;   // 0..15 -> rows rg*4..+3
    int hg = t & 3;    // 0..3  -> heads hg*4..+3
    float acc[4][4];
#pragma unroll
    for (int i = 0; i < 4; i++)
#pragma unroll
        for (int j = 0; j < 4; j++) acc[i][j] = 0.f;

    for (int kt = 0; kt < DIM; kt += 64) {
#pragma unroll 8
        for (int r = 0; r < 64; r++)
            xs[t][r] = x[(size_t)(s0 + r) * DIM + kt + t];
#pragma unroll
        for (int h = 0; h < NH; h++)
            qs[t][h] = g_qW[h * DIM + kt + t];
        __syncthreads();
#pragma unroll 8
        for (int k = 0; k < 64; k++) {
            float4 xv = *reinterpret_cast<const float4*>(&xs[k][rg * 4]);
            float4 qv = *reinterpret_cast<const float4*>(&qs[k][hg * 4]);
            float ax[4] = {xv.x, xv.y, xv.z, xv.w};
            float aq[4] = {qv.x, qv.y, qv.z, qv.w};
#pragma unroll
            for (int i = 0; i < 4; i++)
#pragma unroll
                for (int j = 0; j < 4; j++) acc[i][j] += ax[i] * aq[j];
        }
        __syncthreads();
    }
#pragma unroll
    for (int j = 0; j < 4; j++) {
        int h = hg * 4 + j;
        float qb = g_qb[h];
#pragma unroll
        for (int i = 0; i < 4; i++)
            g_attn[h * SEQ + s0 + rg * 4 + i] = (acc[i][j] + qb) * RSQRT_D;
    }
}

// ---------------- K2: softmax per head (in place) ----------------
__global__ void __launch_bounds__(1024) k_softmax() {
    __shared__ float red[32];
    int h = blockIdx.x, t = threadIdx.x;
    float* L = g_attn + h * SEQ;
    float vals[8];
    float m = -1e30f;
#pragma unroll
    for (int i = 0; i < 8; i++) { vals[i] = L[t + i * 1024]; m = fmaxf(m, vals[i]); }
#pragma unroll
    for (int o = 16; o; o >>= 1) m = fmaxf(m, __shfl_xor_sync(0xffffffffu, m, o));
    if ((t & 31) == 0) red[t >> 5] = m;
    __syncthreads();
    m = red[0];
#pragma unroll
    for (int i = 1; i < 32; i++) m = fmaxf(m, red[i]);

    float sum = 0.f;
#pragma unroll
    for (int i = 0; i < 8; i++) { vals[i] = __expf(vals[i] - m); sum += vals[i]; }
#pragma unroll
    for (int o = 16; o; o >>= 1) sum += __shfl_xor_sync(0xffffffffu, sum, o);
    __syncthreads();
    if ((t & 31) == 0) red[t >> 5] = sum;
    __syncthreads();
    float tot = 0.f;
#pragma unroll
    for (int i = 0; i < 32; i++) tot += red[i];
    float rinv = 1.0f / tot;
#pragma unroll
    for (int i = 0; i < 8; i++) L[t + i * 1024] = vals[i] * rinv;
}

// ---------------- K3: ctx partials = attn @ x (split-K) ----------------
// grid (64, 2), 256 threads. Each CTA: 128 s-rows x 1024 j-cols (4 j/thread).
__global__ void __launch_bounds__(256) k_ctx(const float* __restrict__ x) {
    __shared__ float as[NH][128];
    int t = threadIdx.x;
    int s0 = blockIdx.x * 128;
    int jb = blockIdx.y * 1024 + t;
#pragma unroll
    for (int i = 0; i < 8; i++) {
        int idx = i * 256 + t;
        as[idx >> 7][idx & 127] = g_attn[(idx >> 7) * SEQ + s0 + (idx & 127)];
    }
    __syncthreads();
    float acc[NH][4];
#pragma unroll
    for (int h = 0; h < NH; h++)
#pragma unroll
        for (int j = 0; j < 4; j++) acc[h][j] = 0.f;

#pragma unroll 2
    for (int s = 0; s < 128; s++) {
        const float* xr = x + (size_t)(s0 + s) * DIM + jb;
        float xv0 = xr[0], xv1 = xr[256], xv2 = xr[512], xv3 = xr[768];
#pragma unroll
        for (int h = 0; h < NH; h++) {
            float a = as[h][s];
            acc[h][0] += a * xv0;
            acc[h][1] += a * xv1;
            acc[h][2] += a * xv2;
            acc[h][3] += a * xv3;
        }
    }
    float* P = g_partial + (size_t)blockIdx.x * NH * DIM;
#pragma unroll
    for (int h = 0; h < NH; h++)
#pragma unroll
        for (int j = 0; j < 4; j++)
            P[h * DIM + blockIdx.y * 1024 + j * 256 + t] = acc[h][j];
}

// K4: reduce partials -> ctx[h][j]
__global__ void k_ctxred() {
    int idx = blockIdx.x * 256 + threadIdx.x;  // 0..32767
    float a = 0.f;
#pragma unroll 8
    for (int c = 0; c < N_SCHUNK; c++) a += g_partial[(size_t)c * NH * DIM + idx];
    g_ctx[idx] = a;
}

// ---------------- K5a: x1[i] = W_v[i] . ctx[head(i)] + b_v[i] ------------
__global__ void k_vproj(const float* __restrict__ Wkv, const float* __restrict__ bkv) {
    int gw = (blockIdx.x * blockDim.x + threadIdx.x) >> 5;  // 0..2047
    int l = threadIdx.x & 31;
    const float* wr = Wkv + (size_t)(DIM + gw) * DIM;
    const float* cr = g_ctx + (gw >> 7) * DIM;
    float a = 0.f;
#pragma unroll 4
    for (int j = l; j < DIM; j += 32) a += wr[j] * cr[j];
#pragma unroll
    for (int o = 16; o; o >>= 1) a += __shfl_xor_sync(0xffffffffu, a, o);
    if (l == 0) g_x1[gw] = a + bkv[DIM + gw];
}

// K5b: h1[p] = W_p1[p] . x1 + b_p1[p]
__global__ void k_proj1(const float* __restrict__ Wp1, const float* __restrict__ bp1) {
    int gw = (blockIdx.x * blockDim.x + threadIdx.x) >> 5;  // 0..511
    int l = threadIdx.x & 31;
    const float* wr = Wp1 + (size_t)gw * DIM;
    float a = 0.f;
#pragma unroll 4
    for (int j = l; j < DIM; j += 32) a += wr[j] * g_x1[j];
#pragma unroll
    for (int o = 16; o; o >>= 1) a += __shfl_xor_sync(0xffffffffu, a, o);
    if (l == 0) g_h1[gw] = a + bp1[gw];
}

// K5c: LayerNorm + ReLU over 512 (one CTA)
__global__ void k_ln(const float* __restrict__ lnw, const float* __restrict__ lnb) {
    __shared__ float red[16];
    int t = threadIdx.x;
    float v = g_h1[t];
    float a = v;
#pragma unroll
    for (int o = 16; o; o >>= 1) a += __shfl_xor_sync(0xffffffffu, a, o);
    if ((t & 31) == 0) red[t >> 5] = a;
    __syncthreads();
    float tot = 0.f;
#pragma unroll
    for (int i = 0; i < 16; i++) tot += red[i];
    float mu = tot * (1.0f / (float)PD);
    float dv = v - mu;
    float a2 = dv * dv;
#pragma unroll
    for (int o = 16; o; o >>= 1) a2 += __shfl_xor_sync(0xffffffffu, a2, o);
    __syncthreads();
    if ((t & 31) == 0) red[t >> 5] = a2;
    __syncthreads();
    float tv = 0.f;
#pragma unroll
    for (int i = 0; i < 16; i++) tv += red[i];
    float var = tv * (1.0f / (float)PD);
    float r = rsqrtf(var + LNEPS);
    g_h1n[t] = fmaxf(dv * r * lnw[t] + lnb[t], 0.0f);
}

// K5d: y[i] = W_p2[i] . relu(h1n) + b_p2[i]
__global__ void k_proj2(const float* __restrict__ Wp2, const float* __restrict__ bp2) {
    int gw = (blockIdx.x * blockDim.x + threadIdx.x) >> 5;  // 0..2047
    int l = threadIdx.x & 31;
    const float* wr = Wp2 + (size_t)gw * PD;
    float a = 0.f;
#pragma unroll 4
    for (int p = l; p < PD; p += 32) a += wr[p] * g_h1n[p];
#pragma unroll
    for (int o = 16; o; o >>= 1) a += __shfl_xor_sync(0xffffffffu, a, o);
    if (l == 0) g_y[gw] = a + bp2[gw];
}

// ---------------- K6: out = x + y (broadcast over rows) ----------------
__global__ void __launch_bounds__(256) k_resid(const float4* __restrict__ x4,
                                               float4* __restrict__ o4) {
    int i = blockIdx.x * 256 + threadIdx.x;  // 0..(SEQ*DIM/4 - 1)
    float4 xv = x4[i];
    float4 yv = *reinterpret_cast<const float4*>(&g_y[(i & 511) * 4]);
    o4[i] = make_float4(xv.x + yv.x, xv.y + yv.y, xv.z + yv.z, xv.w + yv.w);
}

// ---------------- launch ----------------
extern "C" void kernel_launch(void* const* d_in, const int* in_sizes, int n_in,
                              void* d_out, int out_size) {
    const float* x    = (const float*)d_in[0];
    const float* q    = (const float*)d_in[1];
    const float* Wkv  = (const float*)d_in[2];
    const float* bkv  = (const float*)d_in[3];
    const float* Wp1  = (const float*)d_in[4];
    const float* bp1  = (const float*)d_in[5];
    const float* Wp2  = (const float*)d_in[6];
    const float* bp2  = (const float*)d_in[7];
    const float* lnw  = (const float*)d_in[8];
    const float* lnb  = (const float*)d_in[9];
    float* out = (float*)d_out;

    k_qw<<<(NH * DIM) / 256, 256>>>(q, Wkv);
    k_qb<<<1, 512>>>(q, bkv);
    k_logits<<<SEQ / 64, 64>>>(x);
    k_softmax<<<NH, 1024>>>();
    k_ctx<<<dim3(N_SCHUNK, 2), 256>>>(x);
    k_ctxred<<<(NH * DIM) / 256, 256>>>();
    k_vproj<<<(DIM * 32) / 256, 256>>>(Wkv, bkv);
    k_proj1<<<(PD * 32) / 256, 256>>>(Wp1, bp1);
    k_ln<<<1, PD>>>(lnw, lnb);
    k_proj2<<<(DIM * 32) / 256, 256>>>(Wp2, bp2);
    k_resid<<<(SEQ * DIM / 4) / 256, 256>>>((const float4*)x, (float4*)out);
}

// round 5
// speedup vs baseline: 2.7080x; 2.7080x over previous
#include <cuda_runtime.h>

#define DIM 2048
#define SEQ 8192
#define NH 16
#define HD 128
#define PD 512
#define LNEPS 1e-5f
#define RSQRT_D 0.08838834764831845f  /* 1/sqrt(128) */

#define LKS 8     /* logits k-split */
#define LKC 256   /* k per chunk */
#define LKT 16    /* k per smem tile */
#define LM  256   /* rows per logits CTA */

#define CS   64   /* ctx: seq rows per chunk */
#define NCH  128  /* ctx chunks */

// ---------------- static scratch ----------------
__device__ __align__(16) float g_qW[NH * DIM];
__device__ __align__(16) float g_logP[LKS][NH * SEQ];    // 4 MB
__device__ __align__(16) float g_attn[NH * SEQ];
__device__ __align__(16) float g_partial[NCH * NH * DIM]; // 16 MB
__device__ __align__(16) float g_ctx[NH * DIM];
__device__ __align__(16) float g_x1[DIM];
__device__ __align__(16) float g_h1n[PD];
__device__ __align__(16) float g_y[DIM];

// ---- K0: qW[h][j] = sum_d q[h*128+d] * W_kv[h*128+d][j] ----
__global__ void __launch_bounds__(256) k_qw(const float* __restrict__ q,
                                            const float* __restrict__ Wkv) {
    int tid = blockIdx.x * 256 + threadIdx.x;   // 0..32767
    int h = tid >> 11;
    int j = tid & (DIM - 1);
    const float* qh = q + h * HD;
    const float* wcol = Wkv + (size_t)(h * HD) * DIM + j;
    float acc = 0.f;
#pragma unroll 16
    for (int d = 0; d < HD; d++)
        acc += qh[d] * wcol[(size_t)d * DIM];
    g_qW[tid] = acc;
}

// ---- K1: logits partials. grid (32, 8), 256 thr. Tile M=256 x N=16, Kchunk=256 ----
__global__ void __launch_bounds__(256) k_logits(const float* __restrict__ x) {
    __shared__ float xs[LKT][LM + 4];   // [k][r]
    __shared__ float qs[LKC][20];       // [k][h]
    int t = threadIdx.x;
    int s0 = blockIdx.x * LM;
    int k0 = blockIdx.y * LKC;
    int rr = t >> 2;   // 0..63
    int kq = t & 3;    // 0..3
    // preload qW chunk (coalesced along k)
#pragma unroll
    for (int i = 0; i < 16; i++) {
        int idx = t + i * 256;           // 0..4095
        int k = idx & 255, h = idx >> 8;
        qs[k][h] = g_qW[h * DIM + k0 + k];
    }
    float acc[4][4];
#pragma unroll
    for (int i = 0; i < 4; i++)
#pragma unroll
        for (int j = 0; j < 4; j++) acc[i][j] = 0.f;
    __syncthreads();

    for (int kc = 0; kc < LKC; kc += LKT) {
#pragma unroll
        for (int m = 0; m < 4; m++) {
            int r = rr + 64 * m;
            float4 v = *reinterpret_cast<const float4*>(
                &x[(size_t)(s0 + r) * DIM + k0 + kc + kq * 4]);
            xs[kq * 4 + 0][r] = v.x;
            xs[kq * 4 + 1][r] = v.y;
            xs[kq * 4 + 2][r] = v.z;
            xs[kq * 4 + 3][r] = v.w;
        }
        __syncthreads();
#pragma unroll
        for (int k = 0; k < LKT; k++) {
            float4 xv = *reinterpret_cast<const float4*>(&xs[k][rr * 4]);
            float4 qv = *reinterpret_cast<const float4*>(&qs[kc + k][kq * 4]);
            float ax[4] = {xv.x, xv.y, xv.z, xv.w};
            float aq[4] = {qv.x, qv.y, qv.z, qv.w};
#pragma unroll
            for (int i = 0; i < 4; i++)
#pragma unroll
                for (int j = 0; j < 4; j++) acc[i][j] += ax[i] * aq[j];
        }
        __syncthreads();
    }
#pragma unroll
    for (int j = 0; j < 4; j++)
#pragma unroll
        for (int i = 0; i < 4; i++)
            g_logP[blockIdx.y][(kq * 4 + j) * SEQ + s0 + rr * 4 + i] = acc[i][j];
}

// ---- K2: softmax per head (sums k-split partials, applies 1/sqrt(d)) ----
__global__ void __launch_bounds__(1024) k_softmax() {
    __shared__ float red[32];
    int h = blockIdx.x, t = threadIdx.x;
    float vals[8];
    float m = -1e30f;
#pragma unroll
    for (int i = 0; i < 8; i++) {
        int idx = t + i * 1024;
        float v = 0.f;
#pragma unroll
        for (int ks = 0; ks < LKS; ks++) v += g_logP[ks][h * SEQ + idx];
        v *= RSQRT_D;
        vals[i] = v;
        m = fmaxf(m, v);
    }
#pragma unroll
    for (int o = 16; o; o >>= 1) m = fmaxf(m, __shfl_xor_sync(0xffffffffu, m, o));
    if ((t & 31) == 0) red[t >> 5] = m;
    __syncthreads();
    m = red[0];
#pragma unroll
    for (int i = 1; i < 32; i++) m = fmaxf(m, red[i]);

    float sum = 0.f;
#pragma unroll
    for (int i = 0; i < 8; i++) { vals[i] = __expf(vals[i] - m); sum += vals[i]; }
#pragma unroll
    for (int o = 16; o; o >>= 1) sum += __shfl_xor_sync(0xffffffffu, sum, o);
    __syncthreads();
    if ((t & 31) == 0) red[t >> 5] = sum;
    __syncthreads();
    float tot = 0.f;
#pragma unroll
    for (int i = 0; i < 32; i++) tot += red[i];
    float rinv = 1.0f / tot;
#pragma unroll
    for (int i = 0; i < 8; i++) g_attn[h * SEQ + t + i * 1024] = vals[i] * rinv;
}

// ---- K3: ctx partials = attn @ x, grid (128, 2), 256 thr ----
__global__ void __launch_bounds__(256) k_ctx(const float* __restrict__ x) {
    __shared__ float as[NH][CS];
    int t = threadIdx.x;
    int s0 = blockIdx.x * CS;
    int jb = blockIdx.y * 1024 + t;
#pragma unroll
    for (int i = 0; i < 4; i++) {
        int idx = t + i * 256;           // 0..1023
        int s = idx & 63, h = idx >> 6;
        as[h][s] = g_attn[h * SEQ + s0 + s];
    }
    __syncthreads();
    float acc[NH][4];
#pragma unroll
    for (int h = 0; h < NH; h++)
#pragma unroll
        for (int j = 0; j < 4; j++) acc[h][j] = 0.f;

#pragma unroll 2
    for (int s = 0; s < CS; s++) {
        const float* xr = x + (size_t)(s0 + s) * DIM + jb;
        float xv0 = xr[0], xv1 = xr[256], xv2 = xr[512], xv3 = xr[768];
#pragma unroll
        for (int h = 0; h < NH; h++) {
            float a = as[h][s];
            acc[h][0] += a * xv0;
            acc[h][1] += a * xv1;
            acc[h][2] += a * xv2;
            acc[h][3] += a * xv3;
        }
    }
    float* P = g_partial + (size_t)blockIdx.x * NH * DIM;
#pragma unroll
    for (int h = 0; h < NH; h++)
#pragma unroll
        for (int j = 0; j < 4; j++)
            P[h * DIM + blockIdx.y * 1024 + j * 256 + t] = acc[h][j];
}

// ---- K4: reduce ctx partials ----
__global__ void __launch_bounds__(256) k_ctxred() {
    int idx = blockIdx.x * 256 + threadIdx.x;  // 0..32767
    float a = 0.f;
#pragma unroll 16
    for (int c = 0; c < NCH; c++) a += g_partial[(size_t)c * NH * DIM + idx];
    g_ctx[idx] = a;
}

// ---- K5a: x1[i] = W_v[i] . ctx[head(i)] + b_v[i] ----
__global__ void __launch_bounds__(256) k_vproj(const float* __restrict__ Wkv,
                                               const float* __restrict__ bkv) {
    int gw = (blockIdx.x * blockDim.x + threadIdx.x) >> 5;  // 0..2047
    int l = threadIdx.x & 31;
    const float4* w4 = reinterpret_cast<const float4*>(Wkv + (size_t)(DIM + gw) * DIM);
    const float4* c4 = reinterpret_cast<const float4*>(g_ctx + (gw >> 7) * DIM);
    float a = 0.f;
#pragma unroll
    for (int i = l; i < DIM / 4; i += 32) {
        float4 wv = w4[i], cv = c4[i];
        a += wv.x * cv.x + wv.y * cv.y + wv.z * cv.z + wv.w * cv.w;
    }
#pragma unroll
    for (int o = 16; o; o >>= 1) a += __shfl_xor_sync(0xffffffffu, a, o);
    if (l == 0) g_x1[gw] = a + bkv[DIM + gw];
}

// ---- K5b: h1 = W_p1 . x1 + b_p1, then LN+ReLU fused in k_ln ----
__device__ __align__(16) float g_h1[PD];
__global__ void __launch_bounds__(256) k_proj1(const float* __restrict__ Wp1,
                                               const float* __restrict__ bp1) {
    int gw = (blockIdx.x * blockDim.x + threadIdx.x) >> 5;  // 0..511
    int l = threadIdx.x & 31;
    const float4* w4 = reinterpret_cast<const float4*>(Wp1 + (size_t)gw * DIM);
    const float4* x4 = reinterpret_cast<const float4*>(g_x1);
    float a = 0.f;
#pragma unroll
    for (int i = l; i < DIM / 4; i += 32) {
        float4 wv = w4[i], xv = x4[i];
        a += wv.x * xv.x + wv.y * xv.y + wv.z * xv.z + wv.w * xv.w;
    }
#pragma unroll
    for (int o = 16; o; o >>= 1) a += __shfl_xor_sync(0xffffffffu, a, o);
    if (l == 0) g_h1[gw] = a + bp1[gw];
}

// ---- K5c: LayerNorm + ReLU over 512 ----
__global__ void __launch_bounds__(PD) k_ln(const float* __restrict__ lnw,
                                           const float* __restrict__ lnb) {
    __shared__ float red[16];
    int t = threadIdx.x;
    float v = g_h1[t];
    float a = v;
#pragma unroll
    for (int o = 16; o; o >>= 1) a += __shfl_xor_sync(0xffffffffu, a, o);
    if ((t & 31) == 0) red[t >> 5] = a;
    __syncthreads();
    float tot = 0.f;
#pragma unroll
    for (int i = 0; i < 16; i++) tot += red[i];
    float mu = tot * (1.0f / (float)PD);
    float dv = v - mu;
    float a2 = dv * dv;
#pragma unroll
    for (int o = 16; o; o >>= 1) a2 += __shfl_xor_sync(0xffffffffu, a2, o);
    __syncthreads();
    if ((t & 31) == 0) red[t >> 5] = a2;
    __syncthreads();
    float tv = 0.f;
#pragma unroll
    for (int i = 0; i < 16; i++) tv += red[i];
    float var = tv * (1.0f / (float)PD);
    float r = rsqrtf(var + LNEPS);
    g_h1n[t] = fmaxf(dv * r * lnw[t] + lnb[t], 0.0f);
}

// ---- K5d: y = W_p2 . relu_h1 + b_p2 ----
__global__ void __launch_bounds__(256) k_proj2(const float* __restrict__ Wp2,
                                               const float* __restrict__ bp2) {
    int gw = (blockIdx.x * blockDim.x + threadIdx.x) >> 5;  // 0..2047
    int l = threadIdx.x & 31;
    const float4* w4 = reinterpret_cast<const float4*>(Wp2 + (size_t)gw * PD);
    const float4* h4 = reinterpret_cast<const float4*>(g_h1n);
    float a = 0.f;
#pragma unroll
    for (int i = l; i < PD / 4; i += 32) {
        float4 wv = w4[i], hv = h4[i];
        a += wv.x * hv.x + wv.y * hv.y + wv.z * hv.z + wv.w * hv.w;
    }
#pragma unroll
    for (int o = 16; o; o >>= 1) a += __shfl_xor_sync(0xffffffffu, a, o);
    if (l == 0) g_y[gw] = a + bp2[gw];
}

// ---- K6: out = x + y ----
__global__ void __launch_bounds__(256) k_resid(const float4* __restrict__ x4,
                                               float4* __restrict__ o4) {
    int i = blockIdx.x * 256 + threadIdx.x;
    float4 xv = x4[i];
    float4 yv = *reinterpret_cast<const float4*>(&g_y[(i & 511) * 4]);
    o4[i] = make_float4(xv.x + yv.x, xv.y + yv.y, xv.z + yv.z, xv.w + yv.w);
}

// ---------------- launch ----------------
extern "C" void kernel_launch(void* const* d_in, const int* in_sizes, int n_in,
                              void* d_out, int out_size) {
    const float* x   = (const float*)d_in[0];
    const float* q   = (const float*)d_in[1];
    const float* Wkv = (const float*)d_in[2];
    const float* bkv = (const float*)d_in[3];
    const float* Wp1 = (const float*)d_in[4];
    const float* bp1 = (const float*)d_in[5];
    const float* Wp2 = (const float*)d_in[6];
    const float* bp2 = (const float*)d_in[7];
    const float* lnw = (const float*)d_in[8];
    const float* lnb = (const float*)d_in[9];
    float* out = (float*)d_out;

    k_qw<<<(NH * DIM) / 256, 256>>>(q, Wkv);
    k_logits<<<dim3(SEQ / LM, LKS), 256>>>(x);
    k_softmax<<<NH, 1024>>>();
    k_ctx<<<dim3(NCH, 2), 256>>>(x);
    k_ctxred<<<(NH * DIM) / 256, 256>>>();
    k_vproj<<<(DIM * 32) / 256, 256>>>(Wkv, bkv);
    k_proj1<<<(PD * 32) / 256, 256>>>(Wp1, bp1);
    k_ln<<<1, PD>>>(lnw, lnb);
    k_proj2<<<(DIM * 32) / 256, 256>>>(Wp2, bp2);
    k_resid<<<(SEQ * DIM / 4) / 256, 256>>>((const float4*)x, (float4*)out);
}